// round 1
// baseline (speedup 1.0000x reference)
#include <cuda_runtime.h>

#define NN 20000
#define EE 320000
#define DD 512
#define BN_EPS 1e-5f

// Scratch (static __device__ arrays — no allocation at runtime)
__device__ float4 g_X4[NN * 128];        // x         [N, 512]  (40.96 MB)
__device__ float4 g_XC4[NN * 256];       // [agg | x_bn] [N, 1024] (81.92 MB)
__device__ float  g_invdeg[NN];          // 1/max(deg,1)

__device__ __forceinline__ float4 f4add(float4 a, float4 b) {
    return make_float4(a.x + b.x, a.y + b.y, a.z + b.z, a.w + b.w);
}

// ---------------------------------------------------------------------------
// Degree
// ---------------------------------------------------------------------------
__global__ void k_zero_deg() {
    int i = blockIdx.x * blockDim.x + threadIdx.x;
    if (i < NN) g_invdeg[i] = 0.f;
}
__global__ void k_count(const int* __restrict__ dst) {
    int e = blockIdx.x * blockDim.x + threadIdx.x;
    if (e < EE) atomicAdd(&g_invdeg[dst[e]], 1.f);
}
__global__ void k_invdeg() {
    int i = blockIdx.x * blockDim.x + threadIdx.x;
    if (i < NN) g_invdeg[i] = 1.f / fmaxf(g_invdeg[i], 1.f);
}

// ---------------------------------------------------------------------------
// Embedding: x = vocab_emb[tokens] + pos_emb[pos]
// ---------------------------------------------------------------------------
__global__ void k_embed(const int* __restrict__ tok, const int* __restrict__ pos,
                        const float4* __restrict__ ve, const float4* __restrict__ pe) {
    unsigned t = blockIdx.x * blockDim.x + threadIdx.x;
    unsigned i = t >> 7, c = t & 127u;
    if (i < NN) {
        g_X4[i * 128 + c] = f4add(ve[(unsigned)tok[i] * 128 + c],
                                  pe[(unsigned)pos[i] * 128 + c]);
    }
}

// ---------------------------------------------------------------------------
// BatchNorm (eval mode) -> XC second half; zero first half (agg accumulator)
// ---------------------------------------------------------------------------
__global__ void k_bn(const float4* __restrict__ ga, const float4* __restrict__ be,
                     const float4* __restrict__ me, const float4* __restrict__ va) {
    unsigned t = blockIdx.x * blockDim.x + threadIdx.x;
    unsigned i = t >> 7, c = t & 127u;
    if (i >= NN) return;
    float4 x = g_X4[i * 128 + c];
    float4 g = ga[c], b = be[c], m = me[c], v = va[c];
    float4 y;
    y.x = (x.x - m.x) * (g.x * rsqrtf(v.x + BN_EPS)) + b.x;
    y.y = (x.y - m.y) * (g.y * rsqrtf(v.y + BN_EPS)) + b.y;
    y.z = (x.z - m.z) * (g.z * rsqrtf(v.z + BN_EPS)) + b.z;
    y.w = (x.w - m.w) * (g.w * rsqrtf(v.w + BN_EPS)) + b.w;
    g_XC4[i * 256 + 128 + c] = y;
    g_XC4[i * 256 + c] = make_float4(0.f, 0.f, 0.f, 0.f);
}

// ---------------------------------------------------------------------------
// Scatter: agg[dst] += x_bn[src]  (float4 vector reduction, no return)
// ---------------------------------------------------------------------------
__global__ void k_scatter(const int* __restrict__ src, const int* __restrict__ dst) {
    unsigned t = blockIdx.x * blockDim.x + threadIdx.x;
    unsigned e = t >> 7, c = t & 127u;
    if (e < EE) {
        unsigned s = (unsigned)__ldg(src + e);
        unsigned d = (unsigned)__ldg(dst + e);
        float4 v = g_XC4[s * 256 + 128 + c];
        float* p = (float*)&g_XC4[d * 256 + c];
        asm volatile("red.global.add.v4.f32 [%0], {%1,%2,%3,%4};"
                     :: "l"(p), "f"(v.x), "f"(v.y), "f"(v.z), "f"(v.w)
                     : "memory");
    }
}

// ---------------------------------------------------------------------------
// Fused dual GEMM: out[i,j] = relu( sum_k A[i,k]*W[j,k] + bias[j] )
//   A = [agg*invdeg | x_bn]  (K=1024),  W = [W_rel | W_root]
// Tiles: 128x128x16, 256 threads, 8x8 micro-tile, single-buffer smem with
// register prefetch of the next k-tile overlapping compute.
// ---------------------------------------------------------------------------
__global__ __launch_bounds__(256, 2) void k_gemm(
    const float* __restrict__ Wrel, const float* __restrict__ Wroot,
    const float4* __restrict__ bias4, float4* __restrict__ out4, int writeX) {
    __shared__ float As[16][132];
    __shared__ float Bs[16][132];

    const int tid = threadIdx.x;
    const int bn = blockIdx.x;            // 0..3
    const int bm = blockIdx.y;            // 0..156
    const int row0 = bm * 128;

    // load-phase mapping: 512 float4 per tile per matrix, 2 per thread
    const int lr = tid >> 2;              // 0..63
    const int lc = tid & 3;               // float4 slot within 16-float row chunk
    const int ar0 = row0 + lr, ar1 = row0 + lr + 64;
    const int br0 = bn * 128 + lr, br1 = br0 + 64;
    const bool v0 = ar0 < NN, v1 = ar1 < NN;
    const float s0 = v0 ? g_invdeg[ar0] : 0.f;
    const float s1 = v1 ? g_invdeg[ar1] : 0.f;

    // compute-phase mapping
    const int tx = tid & 15, ty = tid >> 4;

    float acc[8][8];
#pragma unroll
    for (int i = 0; i < 8; i++)
#pragma unroll
        for (int j = 0; j < 8; j++) acc[i][j] = 0.f;

    float4 a0, a1, b0, b1;

#define LOADTILE(KT)                                                          \
    {                                                                         \
        const int kt_ = (KT);                                                 \
        a0 = make_float4(0.f, 0.f, 0.f, 0.f);                                 \
        a1 = a0;                                                              \
        if (v0) a0 = g_XC4[(unsigned)ar0 * 256 + kt_ * 4 + lc];               \
        if (v1) a1 = g_XC4[(unsigned)ar1 * 256 + kt_ * 4 + lc];               \
        if (kt_ < 32) {                                                       \
            a0.x *= s0; a0.y *= s0; a0.z *= s0; a0.w *= s0;                   \
            a1.x *= s1; a1.y *= s1; a1.z *= s1; a1.w *= s1;                   \
        }                                                                     \
        const float4* Bp = (const float4*)((kt_ < 32) ? Wrel : Wroot);        \
        const int kk4 = (kt_ & 31) * 4 + lc;                                  \
        b0 = Bp[(unsigned)br0 * 128 + kk4];                                   \
        b1 = Bp[(unsigned)br1 * 128 + kk4];                                   \
    }

    LOADTILE(0);

#pragma unroll 1
    for (int kt = 0; kt < 64; ++kt) {
        __syncthreads();
        As[lc * 4 + 0][lr] = a0.x; As[lc * 4 + 1][lr] = a0.y;
        As[lc * 4 + 2][lr] = a0.z; As[lc * 4 + 3][lr] = a0.w;
        As[lc * 4 + 0][lr + 64] = a1.x; As[lc * 4 + 1][lr + 64] = a1.y;
        As[lc * 4 + 2][lr + 64] = a1.z; As[lc * 4 + 3][lr + 64] = a1.w;
        Bs[lc * 4 + 0][lr] = b0.x; Bs[lc * 4 + 1][lr] = b0.y;
        Bs[lc * 4 + 2][lr] = b0.z; Bs[lc * 4 + 3][lr] = b0.w;
        Bs[lc * 4 + 0][lr + 64] = b1.x; Bs[lc * 4 + 1][lr + 64] = b1.y;
        Bs[lc * 4 + 2][lr + 64] = b1.z; Bs[lc * 4 + 3][lr + 64] = b1.w;
        __syncthreads();

        if (kt < 63) LOADTILE(kt + 1);   // gmem loads overlap compute below

#pragma unroll
        for (int kk = 0; kk < 16; kk++) {
            float4 t0 = *(const float4*)&As[kk][ty * 4];
            float4 t1 = *(const float4*)&As[kk][ty * 4 + 64];
            float4 t2 = *(const float4*)&Bs[kk][tx * 4];
            float4 t3 = *(const float4*)&Bs[kk][tx * 4 + 64];
            float a[8] = {t0.x, t0.y, t0.z, t0.w, t1.x, t1.y, t1.z, t1.w};
            float b[8] = {t2.x, t2.y, t2.z, t2.w, t3.x, t3.y, t3.z, t3.w};
#pragma unroll
            for (int i = 0; i < 8; i++)
#pragma unroll
                for (int j = 0; j < 8; j++)
                    acc[i][j] = fmaf(a[i], b[j], acc[i][j]);
        }
    }
#undef LOADTILE

    float4* O = writeX ? g_X4 : out4;
    const int col4a = bn * 32 + tx;
    const int col4b = col4a + 16;
    const float4 bba = bias4[col4a];
    const float4 bbb = bias4[col4b];

#pragma unroll
    for (int i = 0; i < 8; i++) {
        const int lrow = (i < 4) ? (ty * 4 + i) : (ty * 4 + 64 + (i - 4));
        const int gr = row0 + lrow;
        if (gr < NN) {
            float4 o;
            o.x = fmaxf(acc[i][0] + bba.x, 0.f);
            o.y = fmaxf(acc[i][1] + bba.y, 0.f);
            o.z = fmaxf(acc[i][2] + bba.z, 0.f);
            o.w = fmaxf(acc[i][3] + bba.w, 0.f);
            O[(unsigned)gr * 128 + col4a] = o;
            o.x = fmaxf(acc[i][4] + bbb.x, 0.f);
            o.y = fmaxf(acc[i][5] + bbb.y, 0.f);
            o.z = fmaxf(acc[i][6] + bbb.z, 0.f);
            o.w = fmaxf(acc[i][7] + bbb.w, 0.f);
            O[(unsigned)gr * 128 + col4b] = o;
        }
    }
}

// ---------------------------------------------------------------------------
extern "C" void kernel_launch(void* const* d_in, const int* in_sizes, int n_in,
                              void* d_out, int out_size) {
    (void)in_sizes; (void)n_in; (void)out_size;
    const int*   tokens = (const int*)d_in[0];
    const int*   pos    = (const int*)d_in[1];
    const int*   ei     = (const int*)d_in[2];
    const int*   src    = ei;
    const int*   dst    = ei + EE;
    const float* ve     = (const float*)d_in[3];
    const float* pe     = (const float*)d_in[4];
    const float* gamma  = (const float*)d_in[5];
    const float* beta   = (const float*)d_in[6];
    const float* mean   = (const float*)d_in[7];
    const float* var    = (const float*)d_in[8];
    const float* Wrel   = (const float*)d_in[9];
    const float* brel   = (const float*)d_in[10];
    const float* Wroot  = (const float*)d_in[11];
    float*       out    = (float*)d_out;

    k_zero_deg<<<(NN + 255) / 256, 256>>>();
    k_count<<<(EE + 255) / 256, 256>>>(dst);
    k_invdeg<<<(NN + 255) / 256, 256>>>();
    k_embed<<<(NN * 128) / 256, 256>>>(tokens, pos, (const float4*)ve, (const float4*)pe);

    for (int l = 0; l < 4; l++) {
        k_bn<<<(NN * 128) / 256, 256>>>(
            (const float4*)(gamma + l * DD), (const float4*)(beta + l * DD),
            (const float4*)(mean + l * DD), (const float4*)(var + l * DD));
        k_scatter<<<(EE * 128) / 256, 256>>>(src, dst);
        k_gemm<<<dim3(4, 157), 256>>>(
            Wrel + (size_t)l * DD * DD, Wroot + (size_t)l * DD * DD,
            (const float4*)(brel + l * DD), (float4*)out, (l == 3) ? 0 : 1);
    }
}

// round 3
// speedup vs baseline: 1.0466x; 1.0466x over previous
#include <cuda_runtime.h>

#define NN 20000
#define EE 320000
#define DD 512
#define BN_EPS 1e-5f

// Scratch (static __device__ arrays — no allocation at runtime)
__device__ float4 g_X4[NN * 128];        // x         [N, 512]  (40.96 MB)
__device__ float4 g_XC4[NN * 256];       // [agg | x_bn] [N, 1024] (81.92 MB)
__device__ float  g_invdeg[NN];          // 1/max(deg,1)

__device__ __forceinline__ float4 f4add(float4 a, float4 b) {
    return make_float4(a.x + b.x, a.y + b.y, a.z + b.z, a.w + b.w);
}

// ---------------------------------------------------------------------------
// Degree
// ---------------------------------------------------------------------------
__global__ void k_zero_deg() {
    int i = blockIdx.x * blockDim.x + threadIdx.x;
    if (i < NN) g_invdeg[i] = 0.f;
}
__global__ void k_count(const int* __restrict__ dst) {
    int e = blockIdx.x * blockDim.x + threadIdx.x;
    if (e < EE) atomicAdd(&g_invdeg[dst[e]], 1.f);
}
__global__ void k_invdeg() {
    int i = blockIdx.x * blockDim.x + threadIdx.x;
    if (i < NN) g_invdeg[i] = 1.f / fmaxf(g_invdeg[i], 1.f);
}

// ---------------------------------------------------------------------------
// Embedding: x = vocab_emb[tokens] + pos_emb[pos]
// ---------------------------------------------------------------------------
__global__ void k_embed(const int* __restrict__ tok, const int* __restrict__ pos,
                        const float4* __restrict__ ve, const float4* __restrict__ pe) {
    unsigned t = blockIdx.x * blockDim.x + threadIdx.x;
    unsigned i = t >> 7, c = t & 127u;
    if (i < NN) {
        g_X4[i * 128 + c] = f4add(ve[(unsigned)tok[i] * 128 + c],
                                  pe[(unsigned)pos[i] * 128 + c]);
    }
}

// ---------------------------------------------------------------------------
// BatchNorm (eval mode) -> XC second half; zero first half (agg accumulator)
// ---------------------------------------------------------------------------
__global__ void k_bn(const float4* __restrict__ ga, const float4* __restrict__ be,
                     const float4* __restrict__ me, const float4* __restrict__ va) {
    unsigned t = blockIdx.x * blockDim.x + threadIdx.x;
    unsigned i = t >> 7, c = t & 127u;
    if (i >= NN) return;
    float4 x = g_X4[i * 128 + c];
    float4 g = ga[c], b = be[c], m = me[c], v = va[c];
    float4 y;
    y.x = (x.x - m.x) * (g.x * rsqrtf(v.x + BN_EPS)) + b.x;
    y.y = (x.y - m.y) * (g.y * rsqrtf(v.y + BN_EPS)) + b.y;
    y.z = (x.z - m.z) * (g.z * rsqrtf(v.z + BN_EPS)) + b.z;
    y.w = (x.w - m.w) * (g.w * rsqrtf(v.w + BN_EPS)) + b.w;
    g_XC4[i * 256 + 128 + c] = y;
    g_XC4[i * 256 + c] = make_float4(0.f, 0.f, 0.f, 0.f);
}

// ---------------------------------------------------------------------------
// Scatter: agg[dst] += x_bn[src]  (float4 vector reduction, no return)
// ---------------------------------------------------------------------------
__global__ void k_scatter(const int* __restrict__ src, const int* __restrict__ dst) {
    unsigned t = blockIdx.x * blockDim.x + threadIdx.x;
    unsigned e = t >> 7, c = t & 127u;
    if (e < EE) {
        unsigned s = (unsigned)__ldg(src + e);
        unsigned d = (unsigned)__ldg(dst + e);
        float4 v = g_XC4[s * 256 + 128 + c];
        float* p = (float*)&g_XC4[d * 256 + c];
        asm volatile("red.global.add.v4.f32 [%0], {%1,%2,%3,%4};"
                     :: "l"(p), "f"(v.x), "f"(v.y), "f"(v.z), "f"(v.w)
                     : "memory");
    }
}

// ---------------------------------------------------------------------------
// Fused dual GEMM: out[i,j] = relu( sum_k A[i,k]*W[j,k] + bias[j] )
//   A = [agg*invdeg | x_bn]  (K=1024),  W = [W_rel | W_root]
// Tiles: 128x128x16, 256 threads, 8x8 micro-tile, single-buffer smem with
// register prefetch of the next k-tile overlapping compute.
// ---------------------------------------------------------------------------
__global__ __launch_bounds__(256, 2) void k_gemm(
    const float* __restrict__ Wrel, const float* __restrict__ Wroot,
    const float4* __restrict__ bias4, float4* __restrict__ out4, int writeX) {
    __shared__ float As[16][132];
    __shared__ float Bs[16][132];

    const int tid = threadIdx.x;
    const int bn = blockIdx.x;            // 0..3
    const int bm = blockIdx.y;            // 0..156
    const int row0 = bm * 128;

    // load-phase mapping: 512 float4 per tile per matrix, 2 per thread
    const int lr = tid >> 2;              // 0..63
    const int lc = tid & 3;               // float4 slot within 16-float row chunk
    const int ar0 = row0 + lr, ar1 = row0 + lr + 64;
    const int br0 = bn * 128 + lr, br1 = br0 + 64;
    const bool v0 = ar0 < NN, v1 = ar1 < NN;
    const float s0 = v0 ? g_invdeg[ar0] : 0.f;
    const float s1 = v1 ? g_invdeg[ar1] : 0.f;

    // compute-phase mapping
    const int tx = tid & 15, ty = tid >> 4;

    float acc[8][8];
#pragma unroll
    for (int i = 0; i < 8; i++)
#pragma unroll
        for (int j = 0; j < 8; j++) acc[i][j] = 0.f;

    float4 a0, a1, b0, b1;

#define LOADTILE(KT)                                                          \
    {                                                                         \
        const int kt_ = (KT);                                                 \
        a0 = make_float4(0.f, 0.f, 0.f, 0.f);                                 \
        a1 = a0;                                                              \
        if (v0) a0 = g_XC4[(unsigned)ar0 * 256 + kt_ * 4 + lc];               \
        if (v1) a1 = g_XC4[(unsigned)ar1 * 256 + kt_ * 4 + lc];               \
        if (kt_ < 32) {                                                       \
            a0.x *= s0; a0.y *= s0; a0.z *= s0; a0.w *= s0;                   \
            a1.x *= s1; a1.y *= s1; a1.z *= s1; a1.w *= s1;                   \
        }                                                                     \
        const float4* Bp = (const float4*)((kt_ < 32) ? Wrel : Wroot);        \
        const int kk4 = (kt_ & 31) * 4 + lc;                                  \
        b0 = Bp[(unsigned)br0 * 128 + kk4];                                   \
        b1 = Bp[(unsigned)br1 * 128 + kk4];                                   \
    }

    LOADTILE(0);

#pragma unroll 1
    for (int kt = 0; kt < 64; ++kt) {
        __syncthreads();
        As[lc * 4 + 0][lr] = a0.x; As[lc * 4 + 1][lr] = a0.y;
        As[lc * 4 + 2][lr] = a0.z; As[lc * 4 + 3][lr] = a0.w;
        As[lc * 4 + 0][lr + 64] = a1.x; As[lc * 4 + 1][lr + 64] = a1.y;
        As[lc * 4 + 2][lr + 64] = a1.z; As[lc * 4 + 3][lr + 64] = a1.w;
        Bs[lc * 4 + 0][lr] = b0.x; Bs[lc * 4 + 1][lr] = b0.y;
        Bs[lc * 4 + 2][lr] = b0.z; Bs[lc * 4 + 3][lr] = b0.w;
        Bs[lc * 4 + 0][lr + 64] = b1.x; Bs[lc * 4 + 1][lr + 64] = b1.y;
        Bs[lc * 4 + 2][lr + 64] = b1.z; Bs[lc * 4 + 3][lr + 64] = b1.w;
        __syncthreads();

        if (kt < 63) LOADTILE(kt + 1);   // gmem loads overlap compute below

#pragma unroll
        for (int kk = 0; kk < 16; kk++) {
            float4 t0 = *(const float4*)&As[kk][ty * 4];
            float4 t1 = *(const float4*)&As[kk][ty * 4 + 64];
            float4 t2 = *(const float4*)&Bs[kk][tx * 4];
            float4 t3 = *(const float4*)&Bs[kk][tx * 4 + 64];
            float a[8] = {t0.x, t0.y, t0.z, t0.w, t1.x, t1.y, t1.z, t1.w};
            float b[8] = {t2.x, t2.y, t2.z, t2.w, t3.x, t3.y, t3.z, t3.w};
#pragma unroll
            for (int i = 0; i < 8; i++)
#pragma unroll
                for (int j = 0; j < 8; j++)
                    acc[i][j] = fmaf(a[i], b[j], acc[i][j]);
        }
    }
#undef LOADTILE

    float4* O = writeX ? g_X4 : out4;
    const int col4a = bn * 32 + tx;
    const int col4b = col4a + 16;
    const float4 bba = bias4[col4a];
    const float4 bbb = bias4[col4b];

#pragma unroll
    for (int i = 0; i < 8; i++) {
        const int lrow = (i < 4) ? (ty * 4 + i) : (ty * 4 + 64 + (i - 4));
        const int gr = row0 + lrow;
        if (gr < NN) {
            float4 o;
            o.x = fmaxf(acc[i][0] + bba.x, 0.f);
            o.y = fmaxf(acc[i][1] + bba.y, 0.f);
            o.z = fmaxf(acc[i][2] + bba.z, 0.f);
            o.w = fmaxf(acc[i][3] + bba.w, 0.f);
            O[(unsigned)gr * 128 + col4a] = o;
            o.x = fmaxf(acc[i][4] + bbb.x, 0.f);
            o.y = fmaxf(acc[i][5] + bbb.y, 0.f);
            o.z = fmaxf(acc[i][6] + bbb.z, 0.f);
            o.w = fmaxf(acc[i][7] + bbb.w, 0.f);
            O[(unsigned)gr * 128 + col4b] = o;
        }
    }
}

// ---------------------------------------------------------------------------
extern "C" void kernel_launch(void* const* d_in, const int* in_sizes, int n_in,
                              void* d_out, int out_size) {
    (void)in_sizes; (void)n_in; (void)out_size;
    const int*   tokens = (const int*)d_in[0];
    const int*   pos    = (const int*)d_in[1];
    const int*   ei     = (const int*)d_in[2];
    const int*   src    = ei;
    const int*   dst    = ei + EE;
    const float* ve     = (const float*)d_in[3];
    const float* pe     = (const float*)d_in[4];
    const float* gamma  = (const float*)d_in[5];
    const float* beta   = (const float*)d_in[6];
    const float* mean   = (const float*)d_in[7];
    const float* var    = (const float*)d_in[8];
    const float* Wrel   = (const float*)d_in[9];
    const float* brel   = (const float*)d_in[10];
    const float* Wroot  = (const float*)d_in[11];
    float*       out    = (float*)d_out;

    k_zero_deg<<<(NN + 255) / 256, 256>>>();
    k_count<<<(EE + 255) / 256, 256>>>(dst);
    k_invdeg<<<(NN + 255) / 256, 256>>>();
    k_embed<<<(NN * 128) / 256, 256>>>(tokens, pos, (const float4*)ve, (const float4*)pe);

    for (int l = 0; l < 4; l++) {
        k_bn<<<(NN * 128) / 256, 256>>>(
            (const float4*)(gamma + l * DD), (const float4*)(beta + l * DD),
            (const float4*)(mean + l * DD), (const float4*)(var + l * DD));
        k_scatter<<<(EE * 128) / 256, 256>>>(src, dst);
        k_gemm<<<dim3(4, 157), 256>>>(
            Wrel + (size_t)l * DD * DD, Wroot + (size_t)l * DD * DD,
            (const float4*)(brel + l * DD), (float4*)out, (l == 3) ? 0 : 1);
    }
}

// round 7
// speedup vs baseline: 1.5605x; 1.4910x over previous
#include <cuda_runtime.h>
#include <cuda_bf16.h>
#include <stdint.h>

#define NN 20000
#define EE 320000
#define DD 512
#define BN_EPS 1e-5f

__device__ float4 g_X4[NN * 128];        // x          [N, 512]
__device__ float4 g_XC4[NN * 256];       // [agg|x_bn] [N, 1024]
__device__ float  g_invdeg[NN];

__device__ __forceinline__ float4 f4add(float4 a, float4 b) {
    return make_float4(a.x + b.x, a.y + b.y, a.z + b.z, a.w + b.w);
}

// ---------------------------------------------------------------------------
__global__ void k_zero_deg() {
    int i = blockIdx.x * blockDim.x + threadIdx.x;
    if (i < NN) g_invdeg[i] = 0.f;
}
__global__ void k_count(const int* __restrict__ dst) {
    int e = blockIdx.x * blockDim.x + threadIdx.x;
    if (e < EE) atomicAdd(&g_invdeg[dst[e]], 1.f);
}
__global__ void k_invdeg() {
    int i = blockIdx.x * blockDim.x + threadIdx.x;
    if (i < NN) g_invdeg[i] = 1.f / fmaxf(g_invdeg[i], 1.f);
}

__global__ void k_embed(const int* __restrict__ tok, const int* __restrict__ pos,
                        const float4* __restrict__ ve, const float4* __restrict__ pe) {
    unsigned t = blockIdx.x * blockDim.x + threadIdx.x;
    unsigned i = t >> 7, c = t & 127u;
    if (i < NN) {
        g_X4[i * 128 + c] = f4add(ve[(unsigned)tok[i] * 128 + c],
                                  pe[(unsigned)pos[i] * 128 + c]);
    }
}

__global__ void k_bn(const float4* __restrict__ ga, const float4* __restrict__ be,
                     const float4* __restrict__ me, const float4* __restrict__ va) {
    unsigned t = blockIdx.x * blockDim.x + threadIdx.x;
    unsigned i = t >> 7, c = t & 127u;
    if (i >= NN) return;
    float4 x = g_X4[i * 128 + c];
    float4 g = ga[c], b = be[c], m = me[c], v = va[c];
    float4 y;
    y.x = (x.x - m.x) * (g.x * rsqrtf(v.x + BN_EPS)) + b.x;
    y.y = (x.y - m.y) * (g.y * rsqrtf(v.y + BN_EPS)) + b.y;
    y.z = (x.z - m.z) * (g.z * rsqrtf(v.z + BN_EPS)) + b.z;
    y.w = (x.w - m.w) * (g.w * rsqrtf(v.w + BN_EPS)) + b.w;
    g_XC4[i * 256 + 128 + c] = y;
    g_XC4[i * 256 + c] = make_float4(0.f, 0.f, 0.f, 0.f);
}

__global__ void k_scatter(const int* __restrict__ src, const int* __restrict__ dst) {
    unsigned t = blockIdx.x * blockDim.x + threadIdx.x;
    unsigned e = t >> 7, c = t & 127u;
    if (e < EE) {
        unsigned s = (unsigned)__ldg(src + e);
        unsigned d = (unsigned)__ldg(dst + e);
        float4 v = g_XC4[s * 256 + 128 + c];
        float* p = (float*)&g_XC4[d * 256 + c];
        asm volatile("red.global.add.v4.f32 [%0], {%1,%2,%3,%4};"
                     :: "l"(p), "f"(v.x), "f"(v.y), "f"(v.z), "f"(v.w)
                     : "memory");
    }
}

// ===========================================================================
// mma.sync bf16 GEMM (arch-agnostic PTX; tcgen05 rejected at compute_103):
//   C[20000x512] = relu( [agg*invdeg | x_bn] @ [Wrel|Wroot]^T + bias )
// 3-term bf16 split: C = Ah Bh + Ah Bl + Al Bh, f32 accum.
// CTA 128x64, Kc=32, 8 warps (4m x 2n), warp tile 32x32.
// smem rows padded to 80 B -> conflict-free ldmatrix (start banks 20r mod 32).
// ===========================================================================
#define ROWB 80
#define SM_AH 0
#define SM_AL (128 * ROWB)          // 10240
#define SM_BH (2 * 128 * ROWB)      // 20480
#define SM_BL (2 * 128 * ROWB + 64 * ROWB)
#define SM_TOT (2 * 128 * ROWB + 2 * 64 * ROWB)   // 30720

__device__ __forceinline__ uint32_t smem_u32(const void* p) {
    uint32_t a;
    asm("{ .reg .u64 t; cvta.to.shared.u64 t, %1; cvt.u32.u64 %0, t; }"
        : "=r"(a) : "l"(p));
    return a;
}

__device__ __forceinline__ void ldm_x4(uint32_t* r, uint32_t addr) {
    asm volatile("ldmatrix.sync.aligned.m8n8.x4.shared.b16 {%0,%1,%2,%3}, [%4];"
                 : "=r"(r[0]), "=r"(r[1]), "=r"(r[2]), "=r"(r[3]) : "r"(addr));
}

__device__ __forceinline__ void mma16816(float* c, const uint32_t* a,
                                         uint32_t b0, uint32_t b1) {
    asm volatile(
        "mma.sync.aligned.m16n8k16.row.col.f32.bf16.bf16.f32 "
        "{%0,%1,%2,%3}, {%4,%5,%6,%7}, {%8,%9}, {%0,%1,%2,%3};"
        : "+f"(c[0]), "+f"(c[1]), "+f"(c[2]), "+f"(c[3])
        : "r"(a[0]), "r"(a[1]), "r"(a[2]), "r"(a[3]), "r"(b0), "r"(b1));
}

__device__ __forceinline__ unsigned pack_hl(float a, float b, unsigned& lo) {
    __nv_bfloat162 h = __floats2bfloat162_rn(a, b);
    float2 hf = __bfloat1622float2(h);
    __nv_bfloat162 l = __floats2bfloat162_rn(a - hf.x, b - hf.y);
    lo = *reinterpret_cast<unsigned*>(&l);
    return *reinterpret_cast<unsigned*>(&h);
}

__global__ __launch_bounds__(256, 2) void k_gemm_mma(
    const float* __restrict__ Wrel, const float* __restrict__ Wroot,
    const float* __restrict__ bias, float* __restrict__ outp, int writeX) {
    __shared__ __align__(128) char sm[SM_TOT];
    const uint32_t smb = smem_u32(sm);

    const int tid = threadIdx.x;
    const int w = tid >> 5, lane = tid & 31;
    const int row0 = blockIdx.y * 128;
    const int nb0 = blockIdx.x * 64;

    // ---- loader mappings ----
    const int arow = tid >> 1;            // 0..127
    const int ahalf = tid & 1;            // 16-float half of 32-float row
    const int agr = row0 + arow;
    const bool aval = agr < NN;
    const float ascale = aval ? g_invdeg[agr] : 0.f;

    const int brow = tid >> 2;            // 0..63
    const int bq = tid & 3;               // 8-float quarter

    // ---- compute mappings ----
    const int wm0 = (w >> 1) * 32;        // warp m-offset in tile
    const int wn0 = (w & 1) * 32;         // warp n-offset
    const int l8 = lane & 7, lq = lane >> 3;

    float acc[2][4][4];
#pragma unroll
    for (int i = 0; i < 2; i++)
#pragma unroll
        for (int j = 0; j < 4; j++)
#pragma unroll
            for (int k = 0; k < 4; k++) acc[i][j][k] = 0.f;

#pragma unroll 1
    for (int c = 0; c < 32; ++c) {
        // -------- load fp32, split hi/lo, store smem --------
        float4 af[4];
        if (aval) {
            const float4* p = &g_XC4[(size_t)agr * 256 + c * 8 + ahalf * 4];
#pragma unroll
            for (int j = 0; j < 4; j++) af[j] = __ldg(p + j);
            if (c < 16) {
#pragma unroll
                for (int j = 0; j < 4; j++) {
                    af[j].x *= ascale; af[j].y *= ascale;
                    af[j].z *= ascale; af[j].w *= ascale;
                }
            }
        } else {
#pragma unroll
            for (int j = 0; j < 4; j++) af[j] = make_float4(0.f, 0.f, 0.f, 0.f);
        }
        float4 bf[2];
        {
            const float4* q = (const float4*)((c < 16) ? Wrel : Wroot) +
                              (size_t)(nb0 + brow) * 128 + (c & 15) * 8 + bq * 2;
            bf[0] = __ldg(q);
            bf[1] = __ldg(q + 1);
        }

        __syncthreads();   // previous chunk's compute done before overwrite

        {
            unsigned h[8], l[8];
#pragma unroll
            for (int j = 0; j < 4; j++) {
                h[j * 2 + 0] = pack_hl(af[j].x, af[j].y, l[j * 2 + 0]);
                h[j * 2 + 1] = pack_hl(af[j].z, af[j].w, l[j * 2 + 1]);
            }
            char* base = sm + arow * ROWB + ahalf * 32;
            *(uint4*)(base + SM_AH) = make_uint4(h[0], h[1], h[2], h[3]);
            *(uint4*)(base + SM_AH + 16) = make_uint4(h[4], h[5], h[6], h[7]);
            *(uint4*)(base + SM_AL) = make_uint4(l[0], l[1], l[2], l[3]);
            *(uint4*)(base + SM_AL + 16) = make_uint4(l[4], l[5], l[6], l[7]);

            unsigned bh0, bh1, bh2, bh3, bl0, bl1, bl2, bl3;
            bh0 = pack_hl(bf[0].x, bf[0].y, bl0);
            bh1 = pack_hl(bf[0].z, bf[0].w, bl1);
            bh2 = pack_hl(bf[1].x, bf[1].y, bl2);
            bh3 = pack_hl(bf[1].z, bf[1].w, bl3);
            char* bb = sm + brow * ROWB + bq * 16;
            *(uint4*)(bb + SM_BH) = make_uint4(bh0, bh1, bh2, bh3);
            *(uint4*)(bb + SM_BL) = make_uint4(bl0, bl1, bl2, bl3);
        }
        __syncthreads();

        // -------- tensor compute: 2 k-steps of k16 --------
#pragma unroll
        for (int ks = 0; ks < 2; ++ks) {
            const int kb = ks * 32;   // byte offset of k16 step (16 bf16 = 32B)
            uint32_t ah[2][4], al[2][4], bh[2][4], bl[2][4];
            // A: lane lq picks (row +8 for odd lq&1, k +16B for lq>>1)
            const int ar = wm0 + (lq & 1) * 8 + l8;
            const uint32_t akb = kb + (lq >> 1) * 16;
#pragma unroll
            for (int mi = 0; mi < 2; mi++) {
                uint32_t addr = smb + (ar + mi * 16) * ROWB + akb;
                ldm_x4(ah[mi], addr + SM_AH);
                ldm_x4(al[mi], addr + SM_AL);
            }
            // B: lane lq picks (n +8 for lq>>1, k +16B for lq&1)
            const int br = wn0 + (lq >> 1) * 8 + l8;
            const uint32_t bkb = kb + (lq & 1) * 16;
#pragma unroll
            for (int ng = 0; ng < 2; ng++) {
                uint32_t addr = smb + (br + ng * 16) * ROWB + bkb;
                ldm_x4(bh[ng], addr + SM_BH);
                ldm_x4(bl[ng], addr + SM_BL);
            }
#pragma unroll
            for (int mi = 0; mi < 2; mi++)
#pragma unroll
                for (int ni = 0; ni < 4; ni++) {
                    const int g = ni >> 1, o = (ni & 1) * 2;
                    mma16816(acc[mi][ni], ah[mi], bh[g][o], bh[g][o + 1]);
                    mma16816(acc[mi][ni], ah[mi], bl[g][o], bl[g][o + 1]);
                    mma16816(acc[mi][ni], al[mi], bh[g][o], bh[g][o + 1]);
                }
        }
    }

    // -------- epilogue: bias + relu, direct float2 stores --------
    float* O = writeX ? (float*)g_X4 : outp;
    const int lg = lane >> 2, lt = lane & 3;
#pragma unroll
    for (int ni = 0; ni < 4; ni++) {
        const int col = nb0 + wn0 + ni * 8 + lt * 2;
        const float b0 = __ldg(&bias[col]);
        const float b1 = __ldg(&bias[col + 1]);
#pragma unroll
        for (int mi = 0; mi < 2; mi++) {
            const int r0 = row0 + wm0 + mi * 16 + lg;
            if (r0 < NN) {
                float2 v;
                v.x = fmaxf(acc[mi][ni][0] + b0, 0.f);
                v.y = fmaxf(acc[mi][ni][1] + b1, 0.f);
                *(float2*)&O[(size_t)r0 * 512 + col] = v;
            }
            const int r1 = r0 + 8;
            if (r1 < NN) {
                float2 v;
                v.x = fmaxf(acc[mi][ni][2] + b0, 0.f);
                v.y = fmaxf(acc[mi][ni][3] + b1, 0.f);
                *(float2*)&O[(size_t)r1 * 512 + col] = v;
            }
        }
    }
}

// ---------------------------------------------------------------------------
extern "C" void kernel_launch(void* const* d_in, const int* in_sizes, int n_in,
                              void* d_out, int out_size) {
    (void)in_sizes; (void)n_in; (void)out_size;
    const int*   tokens = (const int*)d_in[0];
    const int*   pos    = (const int*)d_in[1];
    const int*   ei     = (const int*)d_in[2];
    const int*   src    = ei;
    const int*   dst    = ei + EE;
    const float* ve     = (const float*)d_in[3];
    const float* pe     = (const float*)d_in[4];
    const float* gamma  = (const float*)d_in[5];
    const float* beta   = (const float*)d_in[6];
    const float* mean   = (const float*)d_in[7];
    const float* var    = (const float*)d_in[8];
    const float* Wrel   = (const float*)d_in[9];
    const float* brel   = (const float*)d_in[10];
    const float* Wroot  = (const float*)d_in[11];
    float*       out    = (float*)d_out;

    k_zero_deg<<<(NN + 255) / 256, 256>>>();
    k_count<<<(EE + 255) / 256, 256>>>(dst);
    k_invdeg<<<(NN + 255) / 256, 256>>>();
    k_embed<<<(NN * 128) / 256, 256>>>(tokens, pos, (const float4*)ve, (const float4*)pe);

    for (int l = 0; l < 4; l++) {
        k_bn<<<(NN * 128) / 256, 256>>>(
            (const float4*)(gamma + l * DD), (const float4*)(beta + l * DD),
            (const float4*)(mean + l * DD), (const float4*)(var + l * DD));
        k_scatter<<<(EE * 128) / 256, 256>>>(src, dst);
        k_gemm_mma<<<dim3(8, 157), 256>>>(
            Wrel + (size_t)l * DD * DD, Wroot + (size_t)l * DD * DD,
            brel + l * DD, out, (l == 3) ? 0 : 1);
    }
}